// round 16
// baseline (speedup 1.0000x reference)
#include <cuda_runtime.h>

// Problem constants (FullChain_58815282152074): N=4096 nodes, d=16, K=16, B=4
#define MB   1024          // nodes per batch (M)
#define NB   4             // num_batches
#define IG   4             // i's per block
#define XS_STRIDE 20       // padded floats per x-row: 8-row LDS.128 phases
                           // cover all 32 banks exactly once (conflict-free)

// Scratch: effective bilinear weight WT[d][e][o] and effective bias
__device__ float g_WT[16 * 16 * 16];
__device__ float g_beff[16];

// ---- packed f32x2 helpers (Blackwell FFMA2) ----
__device__ __forceinline__ unsigned long long ffma2(unsigned long long a,
                                                    unsigned long long b,
                                                    unsigned long long c) {
    unsigned long long d;
    asm("fma.rn.f32x2 %0, %1, %2, %3;" : "=l"(d) : "l"(a), "l"(b), "l"(c));
    return d;
}
__device__ __forceinline__ unsigned long long pack2(float lo, float hi) {
    unsigned long long d;
    asm("mov.b64 %0, {%1, %2};"
        : "=l"(d) : "r"(__float_as_uint(lo)), "r"(__float_as_uint(hi)));
    return d;
}
__device__ __forceinline__ float2 unpack2(unsigned long long v) {
    unsigned int lo, hi;
    asm("mov.b64 {%0, %1}, %2;" : "=r"(lo), "=r"(hi) : "l"(v));
    return make_float2(__uint_as_float(lo), __uint_as_float(hi));
}

// ---------------------------------------------------------------------------
// Kernel A: fold W3@W2 into the bilinear form.
//   C[o,k]     = sum_t W3[o,t] * W2[t,k]
//   WT[d,e,o]  = sum_k C[o,k] * W_bil[k,d,e]     (stored [d][e][o])
//   beff[o]    = sum_k C[o,k]*b_bil[k] + sum_t W3[o,t]*b2[t] + b3[o]
// ---------------------------------------------------------------------------
__global__ void prep_kernel(const float* __restrict__ W_bil,
                            const float* __restrict__ b_bil,
                            const float* __restrict__ W2,
                            const float* __restrict__ b2,
                            const float* __restrict__ W3,
                            const float* __restrict__ b3) {
    __shared__ float Cs[256];
    int tid = threadIdx.x;
    {
        int o = tid >> 4, k = tid & 15;
        float s = 0.f;
#pragma unroll
        for (int t = 0; t < 16; ++t) s += W3[o * 16 + t] * W2[t * 16 + k];
        Cs[tid] = s;
    }
    __syncthreads();
    {
        int d = tid >> 4, e = tid & 15;
#pragma unroll
        for (int o = 0; o < 16; ++o) {
            float s = 0.f;
#pragma unroll
            for (int k = 0; k < 16; ++k)
                s += Cs[o * 16 + k] * W_bil[k * 256 + d * 16 + e];
            g_WT[(d * 16 + e) * 16 + o] = s;
        }
    }
    if (tid < 16) {
        int o = tid;
        float s = b3[o];
#pragma unroll
        for (int k = 0; k < 16; ++k) s += Cs[o * 16 + k] * b_bil[k];
#pragma unroll
        for (int t = 0; t < 16; ++t) s += W3[o * 16 + t] * b2[t];
        g_beff[o] = s;
    }
}

// ---------------------------------------------------------------------------
// Kernel B (e-pair dual-stream body on the conflict-free stride-20 layout):
//   One block per (b, group of IG=4 i's).  256 threads, 2 CTAs/SM.
//   Phase 0: stage batch X (1024 rows x 20-float padded stride).  An 8-row
//            LDS.128 phase maps rows to bank offsets {0,20,8,28,16,4,24,12}
//            mod 32 — all banks exactly once (stride-16 is 4-WAY CONFLICTED:
//            banks wrap every 128B; this was R8/R9/R15's regression).
//   Phase 1: T_i[e][o] for 4 i's, PAIR-INTERLEAVED over e:
//            T2sm[ii][e/2][o][2] = {T[e even], T[e odd]}   (256 floats/i).
//   Phase 2: lane = (j-slot = lane>>2, o-quad = lane&3); T2 for the o-quad
//            in 32 u64 regs.  Each iteration: TWO j's (streams A/B, 64 rows
//            apart); all 8 LDS.128 issue first; 8 interleaved FFMA2 chains;
//            x e-pairs arrive pre-packed from the u64 loads (zero pack2);
//            bias pre-seeded in lo half, final fold lo+hi.
// ---------------------------------------------------------------------------
__global__ __launch_bounds__(256, 2) void edge_kernel(const float* __restrict__ nodes,
                                                      float* __restrict__ out) {
    extern __shared__ float smem[];
    float* xs   = smem;                      // [MB][XS_STRIDE]  80KB
    float* T2sm = smem + MB * XS_STRIDE;     // [IG][256]        4KB
    float* sbe  = T2sm + IG * 256;           // [16]

    const int tid = threadIdx.x;
    const int b   = blockIdx.x >> 8;         // 256 i-groups per batch
    const int ig  = blockIdx.x & 255;
    const int i0  = ig * IG;

    // ---- Phase 0: stage batch X into padded shared ----
    const float4* __restrict__ Xg = (const float4*)(nodes + (size_t)b * (MB * 16));
#pragma unroll
    for (int k = 0; k < 16; ++k) {
        int idx = tid + k * 256;             // float4 index, coalesced
        float4 v = Xg[idx];
        int row = idx >> 2, c = idx & 3;
        *(float4*)(xs + row * XS_STRIDE + c * 4) = v;
    }
    if (tid < 16) sbe[tid] = g_beff[tid];
    __syncthreads();

    // ---- Phase 1: T for 4 i's, pair-interleaved over e (tid = e*16+o) ----
    {
        const int e = tid >> 4, o = tid & 15;
        float t0 = 0.f, t1 = 0.f, t2 = 0.f, t3 = 0.f;
#pragma unroll
        for (int d = 0; d < 16; ++d) {
            float w = g_WT[d * 256 + tid];
            t0 += xs[(i0 + 0) * XS_STRIDE + d] * w;
            t1 += xs[(i0 + 1) * XS_STRIDE + d] * w;
            t2 += xs[(i0 + 2) * XS_STRIDE + d] * w;
            t3 += xs[(i0 + 3) * XS_STRIDE + d] * w;
        }
        const int po = (e >> 1) * 32 + o * 2 + (e & 1);
        T2sm[0 * 256 + po] = t0;
        T2sm[1 * 256 + po] = t1;
        T2sm[2 * 256 + po] = t2;
        T2sm[3 * 256 + po] = t3;
    }
    __syncthreads();

    // ---- Phase 2: edges, dual-stream, e-pair packed ----
    const int lane = tid & 31;
    const int warp = tid >> 5;
    const int q    = lane & 3;               // o-quad: outputs [4q, 4q+4)
    const int slot = lane >> 2;              // j-slot within warp (0..7)

    // bias in lo half, 0 in hi: final lo+hi fold includes bias exactly once
    const unsigned long long bias0 = pack2(sbe[4 * q + 0], 0.f);
    const unsigned long long bias1 = pack2(sbe[4 * q + 1], 0.f);
    const unsigned long long bias2v = pack2(sbe[4 * q + 2], 0.f);
    const unsigned long long bias3 = pack2(sbe[4 * q + 3], 0.f);

    const int jb = warp * 128 + slot;        // stream A base; B = A + 64
    const float* __restrict__ xbase = xs + jb * XS_STRIDE;

#pragma unroll 1
    for (int ii = 0; ii < IG; ++ii) {
        const int i = i0 + ii;

        // T2 for this lane's o-quad -> 32 u64 registers
        unsigned long long Ta[8], Tb[8], Tc[8], Td[8];
#pragma unroll
        for (int ep = 0; ep < 8; ++ep) {
            const float* base = T2sm + ii * 256 + ep * 32 + q * 8;
            ulonglong2 u = *(const ulonglong2*)(base);
            ulonglong2 v = *(const ulonglong2*)(base + 4);
            Ta[ep] = u.x; Tb[ep] = u.y; Tc[ep] = v.x; Td[ep] = v.y;
        }

        float* __restrict__ outBase =
            out + (size_t)(b * MB + i) * (MB - 1) * 16 + q * 4;

#pragma unroll 1
        for (int jj = 0; jj < 8; ++jj) {
            const int jA = jb + jj * 8;      // stream A
            const int jB = jA + 64;          // stream B

            // ALL loads first: 8 LDS.128 (rows 80B apart, 16B aligned)
            const float* xrA = xbase + jj * (8 * XS_STRIDE);
            const ulonglong2* pA = (const ulonglong2*)xrA;
            ulonglong2 a0 = pA[0], a1 = pA[1], a2 = pA[2], a3 = pA[3];
            const ulonglong2* pB = (const ulonglong2*)(xrA + 64 * XS_STRIDE);
            ulonglong2 b0 = pB[0], b1 = pB[1], b2 = pB[2], b3v = pB[3];

            unsigned long long A0 = bias0, A1 = bias1, A2 = bias2v, A3 = bias3;
            unsigned long long B0 = bias0, B1 = bias1, B2 = bias2v, B3 = bias3;

            unsigned long long xpA[8] = {a0.x, a0.y, a1.x, a1.y,
                                         a2.x, a2.y, a3.x, a3.y};
            unsigned long long xpB[8] = {b0.x, b0.y, b1.x, b1.y,
                                         b2.x, b2.y, b3v.x, b3v.y};

            // 8 interleaved FFMA2 chains, zero packing
#pragma unroll
            for (int ep = 0; ep < 8; ++ep) {
                A0 = ffma2(Ta[ep], xpA[ep], A0);
                A1 = ffma2(Tb[ep], xpA[ep], A1);
                A2 = ffma2(Tc[ep], xpA[ep], A2);
                A3 = ffma2(Td[ep], xpA[ep], A3);
                B0 = ffma2(Ta[ep], xpB[ep], B0);
                B1 = ffma2(Tb[ep], xpB[ep], B1);
                B2 = ffma2(Tc[ep], xpB[ep], B2);
                B3 = ffma2(Td[ep], xpB[ep], B3);
            }

            if (jA != i) {
                const int r = jA - (jA > i);
                float2 f0 = unpack2(A0), f1 = unpack2(A1);
                float2 f2 = unpack2(A2), f3 = unpack2(A3);
                *(float4*)(outBase + (size_t)r * 16) =
                    make_float4(f0.x + f0.y, f1.x + f1.y,
                                f2.x + f2.y, f3.x + f3.y);
            }
            if (jB != i) {
                const int r = jB - (jB > i);
                float2 f0 = unpack2(B0), f1 = unpack2(B1);
                float2 f2 = unpack2(B2), f3 = unpack2(B3);
                *(float4*)(outBase + (size_t)r * 16) =
                    make_float4(f0.x + f0.y, f1.x + f1.y,
                                f2.x + f2.y, f3.x + f3.y);
            }
        }
    }
}

extern "C" void kernel_launch(void* const* d_in, const int* in_sizes, int n_in,
                              void* d_out, int out_size) {
    const float* nodes = (const float*)d_in[0];
    const float* W_bil = (const float*)d_in[1];
    const float* b_bil = (const float*)d_in[2];
    const float* W2    = (const float*)d_in[3];
    const float* b2    = (const float*)d_in[4];
    const float* W3    = (const float*)d_in[5];
    const float* b3    = (const float*)d_in[6];
    float* out = (float*)d_out;

    const int smem_bytes = (MB * XS_STRIDE + IG * 256 + 16) * (int)sizeof(float);
    static bool attr_set = false;
    if (!attr_set) {
        cudaFuncSetAttribute(edge_kernel,
                             cudaFuncAttributeMaxDynamicSharedMemorySize,
                             smem_bytes);
        attr_set = true;
    }

    prep_kernel<<<1, 256>>>(W_bil, b_bil, W2, b2, W3, b3);
    edge_kernel<<<NB * (MB / IG), 256, smem_bytes>>>(nodes, out);
}

// round 17
// speedup vs baseline: 1.0014x; 1.0014x over previous
#include <cuda_runtime.h>

// Problem constants (FullChain_58815282152074): N=4096 nodes, d=16, K=16, B=4
#define MB   1024          // nodes per batch (M)
#define NB   4             // num_batches
#define IG   8             // i's per block (amortizes Phase 0/1 overhead)
#define XS_STRIDE 20       // padded floats per x-row (champion R14 layout)

// Scratch: effective bilinear weight WT[d][e][o] and effective bias
__device__ float g_WT[16 * 16 * 16];
__device__ float g_beff[16];

// ---- packed f32x2 helpers (Blackwell FFMA2) ----
__device__ __forceinline__ unsigned long long ffma2(unsigned long long a,
                                                    unsigned long long b,
                                                    unsigned long long c) {
    unsigned long long d;
    asm("fma.rn.f32x2 %0, %1, %2, %3;" : "=l"(d) : "l"(a), "l"(b), "l"(c));
    return d;
}
__device__ __forceinline__ unsigned long long pack2(float lo, float hi) {
    unsigned long long d;
    asm("mov.b64 %0, {%1, %2};"
        : "=l"(d) : "r"(__float_as_uint(lo)), "r"(__float_as_uint(hi)));
    return d;
}
__device__ __forceinline__ float2 unpack2(unsigned long long v) {
    unsigned int lo, hi;
    asm("mov.b64 {%0, %1}, %2;" : "=r"(lo), "=r"(hi) : "l"(v));
    return make_float2(__uint_as_float(lo), __uint_as_float(hi));
}

// ---------------------------------------------------------------------------
// Kernel A: fold W3@W2 into the bilinear form.
//   C[o,k]     = sum_t W3[o,t] * W2[t,k]
//   WT[d,e,o]  = sum_k C[o,k] * W_bil[k,d,e]     (stored [d][e][o])
//   beff[o]    = sum_k C[o,k]*b_bil[k] + sum_t W3[o,t]*b2[t] + b3[o]
// ---------------------------------------------------------------------------
__global__ void prep_kernel(const float* __restrict__ W_bil,
                            const float* __restrict__ b_bil,
                            const float* __restrict__ W2,
                            const float* __restrict__ b2,
                            const float* __restrict__ W3,
                            const float* __restrict__ b3) {
    __shared__ float Cs[256];
    int tid = threadIdx.x;
    {
        int o = tid >> 4, k = tid & 15;
        float s = 0.f;
#pragma unroll
        for (int t = 0; t < 16; ++t) s += W3[o * 16 + t] * W2[t * 16 + k];
        Cs[tid] = s;
    }
    __syncthreads();
    {
        int d = tid >> 4, e = tid & 15;
#pragma unroll
        for (int o = 0; o < 16; ++o) {
            float s = 0.f;
#pragma unroll
            for (int k = 0; k < 16; ++k)
                s += Cs[o * 16 + k] * W_bil[k * 256 + d * 16 + e];
            g_WT[(d * 16 + e) * 16 + o] = s;
        }
    }
    if (tid < 16) {
        int o = tid;
        float s = b3[o];
#pragma unroll
        for (int k = 0; k < 16; ++k) s += Cs[o * 16 + k] * b_bil[k];
#pragma unroll
        for (int t = 0; t < 16; ++t) s += W3[o * 16 + t] * b2[t];
        g_beff[o] = s;
    }
}

// ---------------------------------------------------------------------------
// Kernel B (champion R14 body, IG=8 amortization):
//   One block per (b, group of IG=8 i's).  256 threads, 2 CTAs/SM.
//   Phase 0: stage batch X (1024 x 16, padded stride 20) into shared —
//            paid once per 8 i's now (was per 4).
//   Phase 1: T_i[e][o] for the 8 i's -> shared.
//   Phase 2 (UNCHANGED R14 body): lane = (j-slot = lane>>2, o-quad = lane&3);
//            T in 32 u64 regs; per iteration TWO j's (streams A/B, 64 rows
//            apart): 8 LDS.128 first, then 4 interleaved FFMA2 chains with
//            pack2(x,x) broadcasts; 2 warp-contiguous STG.128.
// ---------------------------------------------------------------------------
__global__ __launch_bounds__(256, 2) void edge_kernel(const float* __restrict__ nodes,
                                                      float* __restrict__ out) {
    extern __shared__ float smem[];
    float* xs  = smem;                       // [MB][XS_STRIDE]  80KB
    float* Tsm = smem + MB * XS_STRIDE;      // [IG][256]        8KB
    float* sbe = Tsm + IG * 256;             // [16]

    const int tid = threadIdx.x;
    const int b   = blockIdx.x >> 7;         // 128 i-groups per batch
    const int ig  = blockIdx.x & 127;
    const int i0  = ig * IG;

    // ---- Phase 0: stage batch X into padded shared ----
    const float4* __restrict__ Xg = (const float4*)(nodes + (size_t)b * (MB * 16));
#pragma unroll
    for (int k = 0; k < 16; ++k) {
        int idx = tid + k * 256;             // float4 index, coalesced
        float4 v = Xg[idx];
        int row = idx >> 2, c = idx & 3;
        *(float4*)(xs + row * XS_STRIDE + c * 4) = v;
    }
    if (tid < 16) sbe[tid] = g_beff[tid];
    __syncthreads();

    // ---- Phase 1: T for the 8 i's (tid = e*16+o) ----
    {
        float t[IG];
#pragma unroll
        for (int ii = 0; ii < IG; ++ii) t[ii] = 0.f;
#pragma unroll
        for (int d = 0; d < 16; ++d) {
            float w = g_WT[d * 256 + tid];
#pragma unroll
            for (int ii = 0; ii < IG; ++ii)
                t[ii] += xs[(i0 + ii) * XS_STRIDE + d] * w;
        }
#pragma unroll
        for (int ii = 0; ii < IG; ++ii) Tsm[ii * 256 + tid] = t[ii];
    }
    __syncthreads();

    // ---- Phase 2: edges, dual-stream (R14 body, unchanged) ----
    const int lane = tid & 31;
    const int warp = tid >> 5;
    const int q    = lane & 3;               // o-quad: outputs [4q, 4q+4)
    const int slot = lane >> 2;              // j-slot within warp (0..7)

    const unsigned long long bias0 = pack2(sbe[4 * q],     sbe[4 * q + 1]);
    const unsigned long long bias1 = pack2(sbe[4 * q + 2], sbe[4 * q + 3]);

    const int jb = warp * 128 + slot;        // stream A base; B = A + 64
    const float* __restrict__ xbase = xs + jb * XS_STRIDE;

#pragma unroll 1
    for (int ii = 0; ii < IG; ++ii) {
        const int i = i0 + ii;

        // T[:, 4q..4q+4) into registers (broadcast LDS.128, conflict-free)
        unsigned long long T0[16], T1[16];
#pragma unroll
        for (int e = 0; e < 16; ++e) {
            ulonglong2 tt = *(const ulonglong2*)(Tsm + ii * 256 + e * 16 + q * 4);
            T0[e] = tt.x;
            T1[e] = tt.y;
        }

        float* __restrict__ outBase =
            out + (size_t)(b * MB + i) * (MB - 1) * 16 + q * 4;

#pragma unroll 1
        for (int jj = 0; jj < 8; ++jj) {
            const int jA = jb + jj * 8;      // stream A: rows [warp*128, +64)
            const int jB = jA + 64;          // stream B: rows [+64, +128)

            // ALL loads first: stream A then stream B (8 LDS.128 total)
            const float* xrA = xbase + jj * (8 * XS_STRIDE);
            float4 a0 = *(const float4*)(xrA);
            float4 a1 = *(const float4*)(xrA + 4);
            float4 a2 = *(const float4*)(xrA + 8);
            float4 a3 = *(const float4*)(xrA + 12);
            const float* xrB = xrA + 64 * XS_STRIDE;
            float4 b0 = *(const float4*)(xrB);
            float4 b1 = *(const float4*)(xrB + 4);
            float4 b2v = *(const float4*)(xrB + 8);
            float4 b3v = *(const float4*)(xrB + 12);

            float xA[16] = {a0.x, a0.y, a0.z, a0.w, a1.x, a1.y, a1.z, a1.w,
                            a2.x, a2.y, a2.z, a2.w, a3.x, a3.y, a3.z, a3.w};
            float xB[16] = {b0.x, b0.y, b0.z, b0.w, b1.x, b1.y, b1.z, b1.w,
                            b2v.x, b2v.y, b2v.z, b2v.w, b3v.x, b3v.y, b3v.z, b3v.w};

            unsigned long long accA0 = bias0, accA1 = bias1;
            unsigned long long accB0 = bias0, accB1 = bias1;

            // interleaved chains: 4 independent FFMA2 dependency chains
#pragma unroll
            for (int e = 0; e < 16; ++e) {
                unsigned long long xxA = pack2(xA[e], xA[e]);
                accA0 = ffma2(T0[e], xxA, accA0);
                accA1 = ffma2(T1[e], xxA, accA1);
                unsigned long long xxB = pack2(xB[e], xB[e]);
                accB0 = ffma2(T0[e], xxB, accB0);
                accB1 = ffma2(T1[e], xxB, accB1);
            }

            if (jA != i) {
                const int r = jA - (jA > i);
                float2 lo = unpack2(accA0);
                float2 hi = unpack2(accA1);
                *(float4*)(outBase + (size_t)r * 16) =
                    make_float4(lo.x, lo.y, hi.x, hi.y);
            }
            if (jB != i) {
                const int r = jB - (jB > i);
                float2 lo = unpack2(accB0);
                float2 hi = unpack2(accB1);
                *(float4*)(outBase + (size_t)r * 16) =
                    make_float4(lo.x, lo.y, hi.x, hi.y);
            }
        }
    }
}

extern "C" void kernel_launch(void* const* d_in, const int* in_sizes, int n_in,
                              void* d_out, int out_size) {
    const float* nodes = (const float*)d_in[0];
    const float* W_bil = (const float*)d_in[1];
    const float* b_bil = (const float*)d_in[2];
    const float* W2    = (const float*)d_in[3];
    const float* b2    = (const float*)d_in[4];
    const float* W3    = (const float*)d_in[5];
    const float* b3    = (const float*)d_in[6];
    float* out = (float*)d_out;

    const int smem_bytes = (MB * XS_STRIDE + IG * 256 + 16) * (int)sizeof(float);
    static bool attr_set = false;
    if (!attr_set) {
        cudaFuncSetAttribute(edge_kernel,
                             cudaFuncAttributeMaxDynamicSharedMemorySize,
                             smem_bytes);
        attr_set = true;
    }

    prep_kernel<<<1, 256>>>(W_bil, b_bil, W2, b2, W3, b3);
    edge_kernel<<<NB * (MB / IG), 256, smem_bytes>>>(nodes, out);
}